// round 6
// baseline (speedup 1.0000x reference)
#include <cuda_runtime.h>
#include <cstddef>

#define N_NODES  100000
#define N_EDGES  3200000
#define D_FEAT   256
#define FILTERS  256

// ---- scratch in __device__ globals (no allocations allowed) ----
__device__ float g_deg[N_NODES];
__device__ float g_dinv[N_NODES];
__device__ float g_h[(size_t)N_NODES * FILTERS];   // dinv-scaled projection, 102.4 MB

// ---------------------------------------------------------------
__global__ void zero_deg_kernel() {
    int i = blockIdx.x * blockDim.x + threadIdx.x;
    if (i < N_NODES) g_deg[i] = 0.0f;
}

__global__ void deg_kernel(const int* __restrict__ row,
                           const float* __restrict__ vals) {
    int e = blockIdx.x * blockDim.x + threadIdx.x;
    if (e < N_EDGES) atomicAdd(&g_deg[row[e]], vals[e]);
}

__global__ void dinv_kernel() {
    int i = blockIdx.x * blockDim.x + threadIdx.x;
    if (i < N_NODES) {
        float d = g_deg[i];
        g_dinv[i] = d > 0.0f ? rsqrtf(d) : 0.0f;
    }
}

__global__ void zero_out_kernel(float4* __restrict__ out) {
    int i = blockIdx.x * blockDim.x + threadIdx.x;
    if (i < N_NODES * (FILTERS / 4)) out[i] = make_float4(0.f, 0.f, 0.f, 0.f);
}

// ---------------------------------------------------------------
// Tiled SGEMM: g_h[m][n] = g_dinv[m] * sum_k x[m][k] * w[k][n]
// BM=64, BN=64, BK=16, 256 threads, 4x4 per thread.
#define BM 64
#define BN 64
#define BK 16

__global__ __launch_bounds__(256) void gemm_kernel(const float* __restrict__ X,
                                                   const float* __restrict__ W) {
    __shared__ __align__(16) float As[BK][BM];
    __shared__ __align__(16) float Bs[BK][BN];

    const int t   = threadIdx.x;
    const int tx  = t & 15;       // 0..15 -> cols tx*4..tx*4+3
    const int ty  = t >> 4;       // 0..15 -> rows ty*4..ty*4+3
    const int row0 = blockIdx.x * BM;
    const int n0   = blockIdx.y * BN;

    // loader mapping
    const int a_row = t >> 2;          // 0..63
    const int a_k4  = (t & 3) * 4;     // 0,4,8,12
    const int b_k   = t >> 4;          // 0..15
    const int b_c4  = (t & 15) * 4;    // 0..60

    float acc[4][4];
#pragma unroll
    for (int i = 0; i < 4; ++i)
#pragma unroll
        for (int j = 0; j < 4; ++j) acc[i][j] = 0.0f;

    for (int k0 = 0; k0 < D_FEAT; k0 += BK) {
        float4 av = make_float4(0.f, 0.f, 0.f, 0.f);
        int gm = row0 + a_row;
        if (gm < N_NODES)
            av = *(const float4*)(X + (size_t)gm * D_FEAT + k0 + a_k4);
        As[a_k4 + 0][a_row] = av.x;
        As[a_k4 + 1][a_row] = av.y;
        As[a_k4 + 2][a_row] = av.z;
        As[a_k4 + 3][a_row] = av.w;

        float4 bv = *(const float4*)(W + (size_t)(k0 + b_k) * FILTERS + n0 + b_c4);
        *(float4*)&Bs[b_k][b_c4] = bv;

        __syncthreads();
#pragma unroll
        for (int k = 0; k < BK; ++k) {
            float4 a = *(const float4*)&As[k][ty * 4];
            float4 b = *(const float4*)&Bs[k][tx * 4];
            acc[0][0] += a.x * b.x; acc[0][1] += a.x * b.y; acc[0][2] += a.x * b.z; acc[0][3] += a.x * b.w;
            acc[1][0] += a.y * b.x; acc[1][1] += a.y * b.y; acc[1][2] += a.y * b.z; acc[1][3] += a.y * b.w;
            acc[2][0] += a.z * b.x; acc[2][1] += a.z * b.y; acc[2][2] += a.z * b.z; acc[2][3] += a.z * b.w;
            acc[3][0] += a.w * b.x; acc[3][1] += a.w * b.y; acc[3][2] += a.w * b.z; acc[3][3] += a.w * b.w;
        }
        __syncthreads();
    }

#pragma unroll
    for (int i = 0; i < 4; ++i) {
        int gm = row0 + ty * 4 + i;
        if (gm < N_NODES) {
            float s = g_dinv[gm];
            float4 o = make_float4(acc[i][0] * s, acc[i][1] * s,
                                   acc[i][2] * s, acc[i][3] * s);
            *(float4*)(g_h + (size_t)gm * FILTERS + n0 + tx * 4) = o;
        }
    }
}

// ---------------------------------------------------------------
// Scatter-aggregate: out[row] += vals[e] * g_h[col].
// 2 edges per warp iteration: half-warp (16 lanes) per edge, 4 float4/lane.
// Boosts per-warp MLP (8 gathers in flight) to cover L2-hit latency.
__global__ __launch_bounds__(256) void scatter_kernel(const int* __restrict__ row,
                                                      const int* __restrict__ col,
                                                      const float* __restrict__ vals,
                                                      float* __restrict__ out) {
    const int lane   = threadIdx.x & 31;
    const int half   = lane >> 4;          // 0 or 1: which edge of the pair
    const int hl     = lane & 15;          // 0..15 within half-warp
    const int warp   = (blockIdx.x * blockDim.x + threadIdx.x) >> 5;
    const int nwarps = (gridDim.x * blockDim.x) >> 5;

    for (int e0 = warp * 2; e0 < N_EDGES; e0 += nwarps * 2) {
        const int e = e0 + half;           // N_EDGES is even; always in range
        const int   r = row[e];
        const int   c = col[e];
        const float v = vals[e];
        const float4* hp = (const float4*)(g_h + (size_t)c * FILTERS) + hl;
        float4*       op = (float4*)(out + (size_t)r * FILTERS) + hl;

        float4 m0 = __ldg(hp +  0);
        float4 m1 = __ldg(hp + 16);
        float4 m2 = __ldg(hp + 32);
        float4 m3 = __ldg(hp + 48);

        m0.x *= v; m0.y *= v; m0.z *= v; m0.w *= v;
        m1.x *= v; m1.y *= v; m1.z *= v; m1.w *= v;
        m2.x *= v; m2.y *= v; m2.z *= v; m2.w *= v;
        m3.x *= v; m3.y *= v; m3.z *= v; m3.w *= v;

        asm volatile("red.global.add.v4.f32 [%0], {%1, %2, %3, %4};"
                     :: "l"(op +  0), "f"(m0.x), "f"(m0.y), "f"(m0.z), "f"(m0.w) : "memory");
        asm volatile("red.global.add.v4.f32 [%0], {%1, %2, %3, %4};"
                     :: "l"(op + 16), "f"(m1.x), "f"(m1.y), "f"(m1.z), "f"(m1.w) : "memory");
        asm volatile("red.global.add.v4.f32 [%0], {%1, %2, %3, %4};"
                     :: "l"(op + 32), "f"(m2.x), "f"(m2.y), "f"(m2.z), "f"(m2.w) : "memory");
        asm volatile("red.global.add.v4.f32 [%0], {%1, %2, %3, %4};"
                     :: "l"(op + 48), "f"(m3.x), "f"(m3.y), "f"(m3.z), "f"(m3.w) : "memory");
    }
}

// ---------------------------------------------------------------
// out = relu(dinv[node] * agg + b)
__global__ void epilogue_kernel(float4* __restrict__ out,
                                const float4* __restrict__ bias) {
    int i = blockIdx.x * blockDim.x + threadIdx.x;   // over N_NODES*64 float4s
    if (i < N_NODES * (FILTERS / 4)) {
        int node = i >> 6;           // 64 float4 per row
        int f4   = i & 63;
        float s = g_dinv[node];
        float4 v = out[i];
        float4 b = bias[f4];
        v.x = fmaxf(fmaf(v.x, s, b.x), 0.0f);
        v.y = fmaxf(fmaf(v.y, s, b.y), 0.0f);
        v.z = fmaxf(fmaf(v.z, s, b.z), 0.0f);
        v.w = fmaxf(fmaf(v.w, s, b.w), 0.0f);
        out[i] = v;
    }
}

// ---------------------------------------------------------------
extern "C" void kernel_launch(void* const* d_in, const int* in_sizes, int n_in,
                              void* d_out, int out_size) {
    const float* x        = (const float*)d_in[0];
    const int*   edge_row = (const int*)d_in[1];
    const int*   edge_col = (const int*)d_in[2];
    const float* edge_val = (const float*)d_in[3];
    const float* w        = (const float*)d_in[4];
    const float* b        = (const float*)d_in[5];
    float*       out      = (float*)d_out;

    // 1) degree + dinv
    zero_deg_kernel<<<(N_NODES + 255) / 256, 256>>>();
    deg_kernel<<<(N_EDGES + 255) / 256, 256>>>(edge_row, edge_val);
    dinv_kernel<<<(N_NODES + 255) / 256, 256>>>();

    // 2) zero output accumulator (must happen every replay — we accumulate into it)
    zero_out_kernel<<<(N_NODES * (FILTERS / 4) + 255) / 256, 256>>>((float4*)out);

    // 3) projection with dinv folded in: g_h = dinv * (x @ w)
    dim3 ggrid((N_NODES + BM - 1) / BM, FILTERS / BN);
    gemm_kernel<<<ggrid, 256>>>(x, w);

    // 4) edge scatter-aggregate with vector atomics
    scatter_kernel<<<2048, 256>>>(edge_row, edge_col, edge_val, out);

    // 5) bias + relu epilogue, second dinv factor applied here
    epilogue_kernel<<<(N_NODES * (FILTERS / 4) + 255) / 256, 256>>>(
        (float4*)out, (const float4*)b);
}

// round 7
// speedup vs baseline: 1.8817x; 1.8817x over previous
#include <cuda_runtime.h>
#include <cstddef>

#define N_NODES  100000
#define N_EDGES  3200000
#define D_FEAT   256
#define FILTERS  256
#define NBLK     ((N_NODES + 255) / 256)   // 391 scan blocks

// ---- scratch in __device__ globals (no allocations allowed) ----
__device__ float g_deg[N_NODES];
__device__ float g_dinv[N_NODES];
__device__ float g_h[(size_t)N_NODES * FILTERS];   // dinv-scaled projection, 102.4 MB
__device__ int   g_cnt[N_NODES];
__device__ int   g_scan[N_NODES];                  // per-block inclusive scan
__device__ int   g_part[NBLK];                     // block totals
__device__ int   g_partx[NBLK];                    // exclusive-scanned block totals
__device__ int   g_rowptr[N_NODES + 1];
__device__ int   g_cursor[N_NODES];
__device__ int   g_ccol[N_EDGES];
__device__ float g_cval[N_EDGES];

// ---------------------------------------------------------------
__global__ void zero_kernel() {
    int i = blockIdx.x * blockDim.x + threadIdx.x;
    if (i < N_NODES) { g_deg[i] = 0.0f; g_cnt[i] = 0; }
}

// histogram: edge count + weighted degree per row
__global__ void hist_kernel(const int* __restrict__ row,
                            const float* __restrict__ vals) {
    int e = blockIdx.x * blockDim.x + threadIdx.x;
    if (e < N_EDGES) {
        int r = row[e];
        atomicAdd(&g_cnt[r], 1);
        atomicAdd(&g_deg[r], vals[e]);
    }
}

__global__ void dinv_kernel() {
    int i = blockIdx.x * blockDim.x + threadIdx.x;
    if (i < N_NODES) {
        float d = g_deg[i];
        g_dinv[i] = d > 0.0f ? rsqrtf(d) : 0.0f;
    }
}

// ---- 3-kernel exclusive scan of g_cnt -> g_rowptr ----
__global__ void scanA_kernel() {
    __shared__ int sh[256];
    int i = blockIdx.x * 256 + threadIdx.x;
    int v = (i < N_NODES) ? g_cnt[i] : 0;
    sh[threadIdx.x] = v;
    __syncthreads();
#pragma unroll
    for (int off = 1; off < 256; off <<= 1) {
        int t = (threadIdx.x >= off) ? sh[threadIdx.x - off] : 0;
        __syncthreads();
        sh[threadIdx.x] += t;
        __syncthreads();
    }
    if (i < N_NODES) g_scan[i] = sh[threadIdx.x];
    if (threadIdx.x == 255) g_part[blockIdx.x] = sh[255];
}

__global__ void scanB_kernel() {       // single block of 512, NBLK=391
    __shared__ int sh[512];
    int t = threadIdx.x;
    int v = (t < NBLK) ? g_part[t] : 0;
    sh[t] = v;
    __syncthreads();
#pragma unroll
    for (int off = 1; off < 512; off <<= 1) {
        int u = (t >= off) ? sh[t - off] : 0;
        __syncthreads();
        sh[t] += u;
        __syncthreads();
    }
    if (t < NBLK) g_partx[t] = sh[t] - v;   // exclusive
}

__global__ void scanC_kernel() {
    int i = blockIdx.x * 256 + threadIdx.x;
    if (i < N_NODES) {
        int excl = g_scan[i] - g_cnt[i] + g_partx[blockIdx.x];
        g_rowptr[i] = excl;
        g_cursor[i] = excl;
    }
    if (i == 0) g_rowptr[N_NODES] = N_EDGES;
}

// fill CSR (order within a row is atomic-race dependent; sums tolerate it)
__global__ void fill_kernel(const int* __restrict__ row,
                            const int* __restrict__ col,
                            const float* __restrict__ vals) {
    int e = blockIdx.x * blockDim.x + threadIdx.x;
    if (e < N_EDGES) {
        int r = row[e];
        int pos = atomicAdd(&g_cursor[r], 1);
        g_ccol[pos] = col[e];
        g_cval[pos] = vals[e];
    }
}

// ---------------------------------------------------------------
// Tiled SGEMM: g_h[m][n] = g_dinv[m] * sum_k x[m][k] * w[k][n]
#define BM 64
#define BN 64
#define BK 16

__global__ __launch_bounds__(256) void gemm_kernel(const float* __restrict__ X,
                                                   const float* __restrict__ W) {
    __shared__ __align__(16) float As[BK][BM];
    __shared__ __align__(16) float Bs[BK][BN];

    const int t   = threadIdx.x;
    const int tx  = t & 15;
    const int ty  = t >> 4;
    const int row0 = blockIdx.x * BM;
    const int n0   = blockIdx.y * BN;

    const int a_row = t >> 2;
    const int a_k4  = (t & 3) * 4;
    const int b_k   = t >> 4;
    const int b_c4  = (t & 15) * 4;

    float acc[4][4];
#pragma unroll
    for (int i = 0; i < 4; ++i)
#pragma unroll
        for (int j = 0; j < 4; ++j) acc[i][j] = 0.0f;

    for (int k0 = 0; k0 < D_FEAT; k0 += BK) {
        float4 av = make_float4(0.f, 0.f, 0.f, 0.f);
        int gm = row0 + a_row;
        if (gm < N_NODES)
            av = *(const float4*)(X + (size_t)gm * D_FEAT + k0 + a_k4);
        As[a_k4 + 0][a_row] = av.x;
        As[a_k4 + 1][a_row] = av.y;
        As[a_k4 + 2][a_row] = av.z;
        As[a_k4 + 3][a_row] = av.w;

        float4 bv = *(const float4*)(W + (size_t)(k0 + b_k) * FILTERS + n0 + b_c4);
        *(float4*)&Bs[b_k][b_c4] = bv;

        __syncthreads();
#pragma unroll
        for (int k = 0; k < BK; ++k) {
            float4 a = *(const float4*)&As[k][ty * 4];
            float4 b = *(const float4*)&Bs[k][tx * 4];
            acc[0][0] += a.x * b.x; acc[0][1] += a.x * b.y; acc[0][2] += a.x * b.z; acc[0][3] += a.x * b.w;
            acc[1][0] += a.y * b.x; acc[1][1] += a.y * b.y; acc[1][2] += a.y * b.z; acc[1][3] += a.y * b.w;
            acc[2][0] += a.z * b.x; acc[2][1] += a.z * b.y; acc[2][2] += a.z * b.z; acc[2][3] += a.z * b.w;
            acc[3][0] += a.w * b.x; acc[3][1] += a.w * b.y; acc[3][2] += a.w * b.z; acc[3][3] += a.w * b.w;
        }
        __syncthreads();
    }

#pragma unroll
    for (int i = 0; i < 4; ++i) {
        int gm = row0 + ty * 4 + i;
        if (gm < N_NODES) {
            float s = g_dinv[gm];
            float4 o = make_float4(acc[i][0] * s, acc[i][1] * s,
                                   acc[i][2] * s, acc[i][3] * s);
            *(float4*)(g_h + (size_t)gm * FILTERS + n0 + tx * 4) = o;
        }
    }
}

// ---------------------------------------------------------------
// CSR aggregation: one warp per node, register accumulation, fused epilogue.
// out[r] = relu(dinv[r] * sum_e val[e]*g_h[col[e]] + bias)
__global__ __launch_bounds__(256) void agg_kernel(float* __restrict__ out,
                                                  const float* __restrict__ bias) {
    const int wid  = (blockIdx.x * blockDim.x + threadIdx.x) >> 5;
    const int lane = threadIdx.x & 31;
    if (wid >= N_NODES) return;

    const int start = g_rowptr[wid];
    const int end   = g_rowptr[wid + 1];

    const float4* H = (const float4*)g_h;
    float4 a0 = make_float4(0.f, 0.f, 0.f, 0.f);
    float4 a1 = a0;

    int i = start;
    for (; i + 1 < end; i += 2) {
        int   c0 = g_ccol[i],     c1 = g_ccol[i + 1];
        float v0 = g_cval[i],     v1 = g_cval[i + 1];
        const float4* h0 = H + (size_t)c0 * 64 + lane;
        const float4* h1 = H + (size_t)c1 * 64 + lane;
        float4 x0 = __ldg(h0);
        float4 y0 = __ldg(h0 + 32);
        float4 x1 = __ldg(h1);
        float4 y1 = __ldg(h1 + 32);
        a0.x = fmaf(v0, x0.x, fmaf(v1, x1.x, a0.x));
        a0.y = fmaf(v0, x0.y, fmaf(v1, x1.y, a0.y));
        a0.z = fmaf(v0, x0.z, fmaf(v1, x1.z, a0.z));
        a0.w = fmaf(v0, x0.w, fmaf(v1, x1.w, a0.w));
        a1.x = fmaf(v0, y0.x, fmaf(v1, y1.x, a1.x));
        a1.y = fmaf(v0, y0.y, fmaf(v1, y1.y, a1.y));
        a1.z = fmaf(v0, y0.z, fmaf(v1, y1.z, a1.z));
        a1.w = fmaf(v0, y0.w, fmaf(v1, y1.w, a1.w));
    }
    if (i < end) {
        int   c0 = g_ccol[i];
        float v0 = g_cval[i];
        const float4* h0 = H + (size_t)c0 * 64 + lane;
        float4 x0 = __ldg(h0);
        float4 y0 = __ldg(h0 + 32);
        a0.x = fmaf(v0, x0.x, a0.x); a0.y = fmaf(v0, x0.y, a0.y);
        a0.z = fmaf(v0, x0.z, a0.z); a0.w = fmaf(v0, x0.w, a0.w);
        a1.x = fmaf(v0, y0.x, a1.x); a1.y = fmaf(v0, y0.y, a1.y);
        a1.z = fmaf(v0, y0.z, a1.z); a1.w = fmaf(v0, y0.w, a1.w);
    }

    const float s = g_dinv[wid];
    const float4* bias4 = (const float4*)bias;
    float4 b0 = __ldg(bias4 + lane);
    float4 b1 = __ldg(bias4 + lane + 32);

    float4 o0, o1;
    o0.x = fmaxf(fmaf(a0.x, s, b0.x), 0.0f);
    o0.y = fmaxf(fmaf(a0.y, s, b0.y), 0.0f);
    o0.z = fmaxf(fmaf(a0.z, s, b0.z), 0.0f);
    o0.w = fmaxf(fmaf(a0.w, s, b0.w), 0.0f);
    o1.x = fmaxf(fmaf(a1.x, s, b1.x), 0.0f);
    o1.y = fmaxf(fmaf(a1.y, s, b1.y), 0.0f);
    o1.z = fmaxf(fmaf(a1.z, s, b1.z), 0.0f);
    o1.w = fmaxf(fmaf(a1.w, s, b1.w), 0.0f);

    float4* op = (float4*)(out + (size_t)wid * FILTERS);
    op[lane]      = o0;
    op[lane + 32] = o1;
}

// ---------------------------------------------------------------
extern "C" void kernel_launch(void* const* d_in, const int* in_sizes, int n_in,
                              void* d_out, int out_size) {
    const float* x        = (const float*)d_in[0];
    const int*   edge_row = (const int*)d_in[1];
    const int*   edge_col = (const int*)d_in[2];
    const float* edge_val = (const float*)d_in[3];
    const float* w        = (const float*)d_in[4];
    const float* b        = (const float*)d_in[5];
    float*       out      = (float*)d_out;

    // 1) counts + weighted degree
    zero_kernel<<<NBLK, 256>>>();
    hist_kernel<<<(N_EDGES + 255) / 256, 256>>>(edge_row, edge_val);
    dinv_kernel<<<NBLK, 256>>>();

    // 2) CSR build: scan + fill
    scanA_kernel<<<NBLK, 256>>>();
    scanB_kernel<<<1, 512>>>();
    scanC_kernel<<<NBLK, 256>>>();
    fill_kernel<<<(N_EDGES + 255) / 256, 256>>>(edge_row, edge_col, edge_val);

    // 3) projection with dinv folded in: g_h = dinv * (x @ w)
    dim3 ggrid((N_NODES + BM - 1) / BM, FILTERS / BN);
    gemm_kernel<<<ggrid, 256>>>(x, w);

    // 4) CSR aggregation with fused dinv/bias/relu epilogue
    agg_kernel<<<(N_NODES * 32 + 255) / 256, 256>>>(out, b);
}

// round 12
// speedup vs baseline: 2.3143x; 1.2299x over previous
#include <cuda_runtime.h>
#include <cuda_fp16.h>
#include <cstddef>

#define N_NODES  100000
#define N_EDGES  3200000
#define D_FEAT   256
#define FILTERS  256
#define NBLK     ((N_NODES + 255) / 256)   // 391 scan blocks

// ---- scratch in __device__ globals (no allocations allowed) ----
__device__ float  g_deg[N_NODES];
__device__ float  g_dinv[N_NODES];
__device__ __half g_h[(size_t)N_NODES * FILTERS];  // dinv-scaled projection, fp16, 51.2 MB (L2-resident)
__device__ int    g_cnt[N_NODES];
__device__ int    g_scan[N_NODES];                 // per-block inclusive scan
__device__ int    g_part[NBLK];                    // block totals
__device__ int    g_partx[NBLK];                   // exclusive-scanned block totals
__device__ int    g_rowptr[N_NODES + 1];
__device__ int    g_cursor[N_NODES];
__device__ int2   g_ecv[N_EDGES];                  // packed (col, val bits)

// ---------------------------------------------------------------
__global__ void zero_kernel() {
    int i = blockIdx.x * blockDim.x + threadIdx.x;
    if (i < N_NODES) { g_deg[i] = 0.0f; g_cnt[i] = 0; }
}

// histogram: edge count + weighted degree per row
__global__ void hist_kernel(const int* __restrict__ row,
                            const float* __restrict__ vals) {
    int e = blockIdx.x * blockDim.x + threadIdx.x;
    if (e < N_EDGES) {
        int r = row[e];
        atomicAdd(&g_cnt[r], 1);
        atomicAdd(&g_deg[r], vals[e]);
    }
}

__global__ void dinv_kernel() {
    int i = blockIdx.x * blockDim.x + threadIdx.x;
    if (i < N_NODES) {
        float d = g_deg[i];
        g_dinv[i] = d > 0.0f ? rsqrtf(d) : 0.0f;
    }
}

// ---- 3-kernel exclusive scan of g_cnt -> g_rowptr ----
__global__ void scanA_kernel() {
    __shared__ int sh[256];
    int i = blockIdx.x * 256 + threadIdx.x;
    int v = (i < N_NODES) ? g_cnt[i] : 0;
    sh[threadIdx.x] = v;
    __syncthreads();
#pragma unroll
    for (int off = 1; off < 256; off <<= 1) {
        int t = (threadIdx.x >= off) ? sh[threadIdx.x - off] : 0;
        __syncthreads();
        sh[threadIdx.x] += t;
        __syncthreads();
    }
    if (i < N_NODES) g_scan[i] = sh[threadIdx.x];
    if (threadIdx.x == 255) g_part[blockIdx.x] = sh[255];
}

__global__ void scanB_kernel() {       // single block of 512, NBLK=391
    __shared__ int sh[512];
    int t = threadIdx.x;
    int v = (t < NBLK) ? g_part[t] : 0;
    sh[t] = v;
    __syncthreads();
#pragma unroll
    for (int off = 1; off < 512; off <<= 1) {
        int u = (t >= off) ? sh[t - off] : 0;
        __syncthreads();
        sh[t] += u;
        __syncthreads();
    }
    if (t < NBLK) g_partx[t] = sh[t] - v;   // exclusive
}

__global__ void scanC_kernel() {
    int i = blockIdx.x * 256 + threadIdx.x;
    if (i < N_NODES) {
        int excl = g_scan[i] - g_cnt[i] + g_partx[blockIdx.x];
        g_rowptr[i] = excl;
        g_cursor[i] = excl;
    }
    if (i == 0) g_rowptr[N_NODES] = N_EDGES;
}

// fill CSR, packed 8B entries (order within a row is race-dependent; sums tolerate it)
__global__ void fill_kernel(const int* __restrict__ row,
                            const int* __restrict__ col,
                            const float* __restrict__ vals) {
    int e = blockIdx.x * blockDim.x + threadIdx.x;
    if (e < N_EDGES) {
        int r = row[e];
        int pos = atomicAdd(&g_cursor[r], 1);
        g_ecv[pos] = make_int2(col[e], __float_as_int(vals[e]));
    }
}

// ---------------------------------------------------------------
// Tiled SGEMM: g_h[m][n] = (half) g_dinv[m] * sum_k x[m][k] * w[k][n]
#define BM 64
#define BN 64
#define BK 16

__global__ __launch_bounds__(256) void gemm_kernel(const float* __restrict__ X,
                                                   const float* __restrict__ W) {
    __shared__ __align__(16) float As[BK][BM];
    __shared__ __align__(16) float Bs[BK][BN];

    const int t   = threadIdx.x;
    const int tx  = t & 15;
    const int ty  = t >> 4;
    const int row0 = blockIdx.x * BM;
    const int n0   = blockIdx.y * BN;

    const int a_row = t >> 2;
    const int a_k4  = (t & 3) * 4;
    const int b_k   = t >> 4;
    const int b_c4  = (t & 15) * 4;

    float acc[4][4];
#pragma unroll
    for (int i = 0; i < 4; ++i)
#pragma unroll
        for (int j = 0; j < 4; ++j) acc[i][j] = 0.0f;

    for (int k0 = 0; k0 < D_FEAT; k0 += BK) {
        float4 av = make_float4(0.f, 0.f, 0.f, 0.f);
        int gm = row0 + a_row;
        if (gm < N_NODES)
            av = *(const float4*)(X + (size_t)gm * D_FEAT + k0 + a_k4);
        As[a_k4 + 0][a_row] = av.x;
        As[a_k4 + 1][a_row] = av.y;
        As[a_k4 + 2][a_row] = av.z;
        As[a_k4 + 3][a_row] = av.w;

        float4 bv = *(const float4*)(W + (size_t)(k0 + b_k) * FILTERS + n0 + b_c4);
        *(float4*)&Bs[b_k][b_c4] = bv;

        __syncthreads();
#pragma unroll
        for (int k = 0; k < BK; ++k) {
            float4 a = *(const float4*)&As[k][ty * 4];
            float4 b = *(const float4*)&Bs[k][tx * 4];
            acc[0][0] += a.x * b.x; acc[0][1] += a.x * b.y; acc[0][2] += a.x * b.z; acc[0][3] += a.x * b.w;
            acc[1][0] += a.y * b.x; acc[1][1] += a.y * b.y; acc[1][2] += a.y * b.z; acc[1][3] += a.y * b.w;
            acc[2][0] += a.z * b.x; acc[2][1] += a.z * b.y; acc[2][2] += a.z * b.z; acc[2][3] += a.z * b.w;
            acc[3][0] += a.w * b.x; acc[3][1] += a.w * b.y; acc[3][2] += a.w * b.z; acc[3][3] += a.w * b.w;
        }
        __syncthreads();
    }

#pragma unroll
    for (int i = 0; i < 4; ++i) {
        int gm = row0 + ty * 4 + i;
        if (gm < N_NODES) {
            float s = g_dinv[gm];
            __half2 h0 = __floats2half2_rn(acc[i][0] * s, acc[i][1] * s);
            __half2 h1 = __floats2half2_rn(acc[i][2] * s, acc[i][3] * s);
            __half2* dst = (__half2*)(g_h + (size_t)gm * FILTERS + n0 + tx * 4);
            dst[0] = h0;
            dst[1] = h1;
        }
    }
}

// ---------------------------------------------------------------
// CSR aggregation: one warp per node. Each lane loads ONE float4 (8 fp16) per
// edge covering filters [lane*8, lane*8+8). 4-edge unroll for MLP.
// out[r] = relu(dinv[r] * sum_e val[e]*g_h[col[e]] + bias)
__global__ __launch_bounds__(256) void agg_kernel(float* __restrict__ out,
                                                  const float* __restrict__ bias) {
    const int wid  = (blockIdx.x * blockDim.x + threadIdx.x) >> 5;
    const int lane = threadIdx.x & 31;
    if (wid >= N_NODES) return;

    const int start = g_rowptr[wid];
    const int end   = g_rowptr[wid + 1];

    const float4* H = (const float4*)g_h;   // 32 float4 per row (256 halfs)
    float a[8];
#pragma unroll
    for (int j = 0; j < 8; ++j) a[j] = 0.0f;

    int i = start;
    for (; i + 3 < end; i += 4) {
        int2 e0 = __ldg(&g_ecv[i]);
        int2 e1 = __ldg(&g_ecv[i + 1]);
        int2 e2 = __ldg(&g_ecv[i + 2]);
        int2 e3 = __ldg(&g_ecv[i + 3]);
        float4 r0 = __ldg(H + (size_t)e0.x * 32 + lane);
        float4 r1 = __ldg(H + (size_t)e1.x * 32 + lane);
        float4 r2 = __ldg(H + (size_t)e2.x * 32 + lane);
        float4 r3 = __ldg(H + (size_t)e3.x * 32 + lane);
        float v0 = __int_as_float(e0.y), v1 = __int_as_float(e1.y);
        float v2 = __int_as_float(e2.y), v3 = __int_as_float(e3.y);

        const __half2* p0 = (const __half2*)&r0;
        const __half2* p1 = (const __half2*)&r1;
        const __half2* p2 = (const __half2*)&r2;
        const __half2* p3 = (const __half2*)&r3;
#pragma unroll
        for (int j = 0; j < 4; ++j) {
            float2 f0 = __half22float2(p0[j]);
            float2 f1 = __half22float2(p1[j]);
            float2 f2 = __half22float2(p2[j]);
            float2 f3 = __half22float2(p3[j]);
            a[2*j]   = fmaf(v0, f0.x, fmaf(v1, f1.x, fmaf(v2, f2.x, fmaf(v3, f3.x, a[2*j]))));
            a[2*j+1] = fmaf(v0, f0.y, fmaf(v1, f1.y, fmaf(v2, f2.y, fmaf(v3, f3.y, a[2*j+1]))));
        }
    }
    for (; i < end; ++i) {
        int2 e0 = __ldg(&g_ecv[i]);
        float4 r0 = __ldg(H + (size_t)e0.x * 32 + lane);
        float v0 = __int_as_float(e0.y);
        const __half2* p0 = (const __half2*)&r0;
#pragma unroll
        for (int j = 0; j < 4; ++j) {
            float2 f0 = __half22float2(p0[j]);
            a[2*j]   = fmaf(v0, f0.x, a[2*j]);
            a[2*j+1] = fmaf(v0, f0.y, a[2*j+1]);
        }
    }

    const float s = g_dinv[wid];
    // bias for filters [lane*8, lane*8+8): two float4s
    const float4* bias4 = (const float4*)bias;
    float4 b0 = __ldg(bias4 + lane * 2);
    float4 b1 = __ldg(bias4 + lane * 2 + 1);

    float4 o0, o1;
    o0.x = fmaxf(fmaf(a[0], s, b0.x), 0.0f);
    o0.y = fmaxf(fmaf(a[1], s, b0.y), 0.0f);
    o0.z = fmaxf(fmaf(a[2], s, b0.z), 0.0f);
    o0.w = fmaxf(fmaf(a[3], s, b0.w), 0.0f);
    o1.x = fmaxf(fmaf(a[4], s, b1.x), 0.0f);
    o1.y = fmaxf(fmaf(a[5], s, b1.y), 0.0f);
    o1.z = fmaxf(fmaf(a[6], s, b1.z), 0.0f);
    o1.w = fmaxf(fmaf(a[7], s, b1.w), 0.0f);

    float4* op = (float4*)(out + (size_t)wid * FILTERS) + lane * 2;
    op[0] = o0;
    op[1] = o1;
}

// ---------------------------------------------------------------
extern "C" void kernel_launch(void* const* d_in, const int* in_sizes, int n_in,
                              void* d_out, int out_size) {
    const float* x        = (const float*)d_in[0];
    const int*   edge_row = (const int*)d_in[1];
    const int*   edge_col = (const int*)d_in[2];
    const float* edge_val = (const float*)d_in[3];
    const float* w        = (const float*)d_in[4];
    const float* b        = (const float*)d_in[5];
    float*       out      = (float*)d_out;

    // 1) counts + weighted degree
    zero_kernel<<<NBLK, 256>>>();
    hist_kernel<<<(N_EDGES + 255) / 256, 256>>>(edge_row, edge_val);
    dinv_kernel<<<NBLK, 256>>>();

    // 2) CSR build: scan + fill
    scanA_kernel<<<NBLK, 256>>>();
    scanB_kernel<<<1, 512>>>();
    scanC_kernel<<<NBLK, 256>>>();
    fill_kernel<<<(N_EDGES + 255) / 256, 256>>>(edge_row, edge_col, edge_val);

    // 3) projection with dinv folded in: g_h = (half) dinv * (x @ w)
    dim3 ggrid((N_NODES + BM - 1) / BM, FILTERS / BN);
    gemm_kernel<<<ggrid, 256>>>(x, w);

    // 4) CSR aggregation with fused dinv/bias/relu epilogue
    agg_kernel<<<(N_NODES * 32 + 255) / 256, 256>>>(out, b);
}

// round 15
// speedup vs baseline: 3.5060x; 1.5149x over previous
#include <cuda_runtime.h>
#include <cuda_fp16.h>
#include <mma.h>
#include <cstdint>
#include <cstddef>

using namespace nvcuda;

#define N_NODES  100000
#define N_EDGES  3200000
#define D_FEAT   256
#define FILTERS  256
#define NBLK     ((N_NODES + 255) / 256)   // 391 scan blocks

// ---- scratch in __device__ globals (no allocations allowed) ----
__device__ float  g_deg[N_NODES];
__device__ float  g_dinv[N_NODES];
__device__ __half g_h[(size_t)N_NODES * FILTERS];  // dinv-scaled projection, fp16, 51.2 MB
__device__ int    g_cnt[N_NODES];
__device__ int    g_scan[N_NODES];
__device__ int    g_part[NBLK];
__device__ int    g_partx[NBLK];
__device__ int    g_rowptr[N_NODES + 1];
__device__ int    g_cursor[N_NODES];
__device__ int2   g_ecv[N_EDGES];                  // packed (col, val bits)
__device__ __half g_wth[D_FEAT * FILTERS];         // w^T hi: [n][k] fp16
__device__ __half g_wtl[D_FEAT * FILTERS];         // w^T lo (residual): [n][k] fp16
__device__ __half g_xh[(size_t)N_NODES * D_FEAT];  // x hi fp16, 51.2 MB
__device__ __half g_xl[(size_t)N_NODES * D_FEAT];  // x lo fp16, 51.2 MB

// ======================= small kernels =======================
__global__ void zero_kernel() {
    int i = blockIdx.x * blockDim.x + threadIdx.x;
    if (i < N_NODES) { g_deg[i] = 0.0f; g_cnt[i] = 0; }
}

__global__ void hist_kernel(const int* __restrict__ row,
                            const float* __restrict__ vals) {
    int e = blockIdx.x * blockDim.x + threadIdx.x;
    if (e < N_EDGES) {
        int r = row[e];
        atomicAdd(&g_cnt[r], 1);
        atomicAdd(&g_deg[r], vals[e]);
    }
}

__global__ void dinv_kernel() {
    int i = blockIdx.x * blockDim.x + threadIdx.x;
    if (i < N_NODES) {
        float d = g_deg[i];
        g_dinv[i] = d > 0.0f ? rsqrtf(d) : 0.0f;
    }
}

__global__ void scanA_kernel() {
    __shared__ int sh[256];
    int i = blockIdx.x * 256 + threadIdx.x;
    int v = (i < N_NODES) ? g_cnt[i] : 0;
    sh[threadIdx.x] = v;
    __syncthreads();
#pragma unroll
    for (int off = 1; off < 256; off <<= 1) {
        int t = (threadIdx.x >= off) ? sh[threadIdx.x - off] : 0;
        __syncthreads();
        sh[threadIdx.x] += t;
        __syncthreads();
    }
    if (i < N_NODES) g_scan[i] = sh[threadIdx.x];
    if (threadIdx.x == 255) g_part[blockIdx.x] = sh[255];
}

__global__ void scanB_kernel() {
    __shared__ int sh[512];
    int t = threadIdx.x;
    int v = (t < NBLK) ? g_part[t] : 0;
    sh[t] = v;
    __syncthreads();
#pragma unroll
    for (int off = 1; off < 512; off <<= 1) {
        int u = (t >= off) ? sh[t - off] : 0;
        __syncthreads();
        sh[t] += u;
        __syncthreads();
    }
    if (t < NBLK) g_partx[t] = sh[t] - v;
}

__global__ void scanC_kernel() {
    int i = blockIdx.x * 256 + threadIdx.x;
    if (i < N_NODES) {
        int excl = g_scan[i] - g_cnt[i] + g_partx[blockIdx.x];
        g_rowptr[i] = excl;
        g_cursor[i] = excl;
    }
    if (i == 0) g_rowptr[N_NODES] = N_EDGES;
}

__global__ void fill_kernel(const int* __restrict__ row,
                            const int* __restrict__ col,
                            const float* __restrict__ vals) {
    int e = blockIdx.x * blockDim.x + threadIdx.x;
    if (e < N_EDGES) {
        int r = row[e];
        int pos = atomicAdd(&g_cursor[r], 1);
        g_ecv[pos] = make_int2(col[e], __float_as_int(vals[e]));
    }
}

// split w into hi/lo fp16 transposed: g_wth/g_wtl[n][k] = split(w[k][n])
__global__ void wsplit_kernel(const float* __restrict__ W) {
    int idx = blockIdx.x * blockDim.x + threadIdx.x;
    if (idx < D_FEAT * FILTERS) {
        int k = idx >> 8, n = idx & 255;
        float f = W[idx];                      // w[k][n]
        __half h = __float2half_rn(f);
        __half l = __float2half_rn(f - __half2float(h));
        g_wth[n * D_FEAT + k] = h;
        g_wtl[n * D_FEAT + k] = l;
    }
}

// split x into hi/lo fp16: 8 elements per thread
__global__ void xsplit_kernel(const float* __restrict__ X) {
    size_t i = (size_t)(blockIdx.x) * blockDim.x + threadIdx.x;   // per 8 elems
    if (i < (size_t)N_NODES * D_FEAT / 8) {
        const float4* xp = (const float4*)X + i * 2;
        float4 v0 = __ldg(xp);
        float4 v1 = __ldg(xp + 1);
        __half h[8], l[8];
        float f[8] = {v0.x, v0.y, v0.z, v0.w, v1.x, v1.y, v1.z, v1.w};
#pragma unroll
        for (int j = 0; j < 8; ++j) {
            h[j] = __float2half_rn(f[j]);
            l[j] = __float2half_rn(f[j] - __half2float(h[j]));
        }
        *((int4*)g_xh + i) = *(int4*)h;
        *((int4*)g_xl + i) = *(int4*)l;
    }
}

// ======================= wmma (HMMA) GEMM =======================
// Per CTA: 64 node rows x 256 filters. 8 warps in 2(m) x 4(n); warp tile 32x64.
// D(fp32) = xh*wh + xl*wh + xh*wl  (~fp32 accuracy); epilogue scales by dinv,
// stores fp16 g_h.
#define BMW   64
#define BKW   64
#define LDA   72                       // padded row stride (halves), 144 B (16B-mult)
#define AH_OFF  0
#define AL_OFF  (AH_OFF + BMW * LDA * 2)            // 9216
#define BH_OFF  (AL_OFF + BMW * LDA * 2)            // 18432
#define BL_OFF  (BH_OFF + FILTERS * LDA * 2)        // 55296
#define SCR_OFF (BL_OFF + FILTERS * LDA * 2)        // 92160
#define GEMM_SMEM (SCR_OFF + 8 * 256 * 4)           // + 8KB scratch = 100352

__global__ __launch_bounds__(256) void gemm_wmma_kernel() {
    extern __shared__ __align__(16) char smem[];
    __half* Ah = (__half*)(smem + AH_OFF);
    __half* Al = (__half*)(smem + AL_OFF);
    __half* Bh = (__half*)(smem + BH_OFF);
    __half* Bl = (__half*)(smem + BL_OFF);

    const int tid  = threadIdx.x;
    const int wid  = tid >> 5;
    const int lane = tid & 31;
    const int wm   = wid & 1;           // 0..1 -> rows wm*32..+32
    const int wn   = wid >> 1;          // 0..3 -> cols wn*64..+64
    const int tile0 = blockIdx.x * BMW;

    wmma::fragment<wmma::accumulator, 16, 16, 16, float> acc[2][4];
#pragma unroll
    for (int i = 0; i < 2; ++i)
#pragma unroll
        for (int j = 0; j < 4; ++j) wmma::fill_fragment(acc[i][j], 0.0f);

    for (int ch = 0; ch < 4; ++ch) {
        const int k0 = ch * BKW;

        // ---- stage A hi/lo [64 x 64] ----
#pragma unroll
        for (int p = 0; p < 2; ++p) {
            int idx = tid + p * 256;          // 0..511 int4s
            int r = idx >> 3, k8 = idx & 7;
            int gm = tile0 + r;
            int4 vh = make_int4(0, 0, 0, 0), vl = vh;
            if (gm < N_NODES) {
                size_t off = ((size_t)gm * D_FEAT + k0 + k8 * 8) >> 3;  // int4 index
                vh = __ldg((const int4*)g_xh + off);
                vl = __ldg((const int4*)g_xl + off);
            }
            *(int4*)(Ah + r * LDA + k8 * 8) = vh;
            *(int4*)(Al + r * LDA + k8 * 8) = vl;
        }
        // ---- stage B hi/lo [256 x 64] (wT layout [n][k]) ----
#pragma unroll
        for (int p = 0; p < 8; ++p) {
            int idx = tid + p * 256;          // 0..2047 int4s
            int n = idx >> 3, k8 = idx & 7;
            size_t off = ((size_t)n * D_FEAT + k0 + k8 * 8) >> 3;
            *(int4*)(Bh + n * LDA + k8 * 8) = __ldg((const int4*)g_wth + off);
            *(int4*)(Bl + n * LDA + k8 * 8) = __ldg((const int4*)g_wtl + off);
        }
        __syncthreads();

        // ---- 4 K-steps of 16, 3 terms ----
#pragma unroll
        for (int ks = 0; ks < 4; ++ks) {
            const int kk = ks * 16;
            wmma::fragment<wmma::matrix_a, 16, 16, 16, __half, wmma::row_major> ah[2], al[2];
#pragma unroll
            for (int i = 0; i < 2; ++i) {
                wmma::load_matrix_sync(ah[i], Ah + (wm * 32 + i * 16) * LDA + kk, LDA);
                wmma::load_matrix_sync(al[i], Al + (wm * 32 + i * 16) * LDA + kk, LDA);
            }
#pragma unroll
            for (int j = 0; j < 4; ++j) {
                wmma::fragment<wmma::matrix_b, 16, 16, 16, __half, wmma::col_major> bh, bl;
                wmma::load_matrix_sync(bh, Bh + (wn * 64 + j * 16) * LDA + kk, LDA);
                wmma::load_matrix_sync(bl, Bl + (wn * 64 + j * 16) * LDA + kk, LDA);
#pragma unroll
                for (int i = 0; i < 2; ++i) {
                    wmma::mma_sync(acc[i][j], ah[i], bh, acc[i][j]);
                    wmma::mma_sync(acc[i][j], al[i], bh, acc[i][j]);
                    wmma::mma_sync(acc[i][j], ah[i], bl, acc[i][j]);
                }
            }
        }
        __syncthreads();
    }

    // ---- epilogue: per-warp scratch -> dinv scale -> fp16 g_h ----
    float* scr = (float*)(smem + SCR_OFF) + wid * 256;
    const int r  = lane >> 1;            // 0..15
    const int c8 = (lane & 1) * 8;       // 0 or 8
#pragma unroll
    for (int i = 0; i < 2; ++i) {
#pragma unroll
        for (int j = 0; j < 4; ++j) {
            wmma::store_matrix_sync(scr, acc[i][j], 16, wmma::mem_row_major);
            __syncwarp();
            const int m = tile0 + wm * 32 + i * 16 + r;
            if (m < N_NODES) {
                const float s = g_dinv[m];
                uint32_t u[4];
#pragma unroll
                for (int q = 0; q < 4; ++q) {
                    __half2 h = __floats2half2_rn(scr[r * 16 + c8 + 2 * q] * s,
                                                  scr[r * 16 + c8 + 2 * q + 1] * s);
                    u[q] = *(uint32_t*)&h;
                }
                *(int4*)(g_h + (size_t)m * FILTERS + wn * 64 + j * 16 + c8) =
                    make_int4(u[0], u[1], u[2], u[3]);
            }
            __syncwarp();
        }
    }
}

// ======================= CSR aggregation =======================
__global__ __launch_bounds__(256) void agg_kernel(float* __restrict__ out,
                                                  const float* __restrict__ bias) {
    const int wid  = (blockIdx.x * blockDim.x + threadIdx.x) >> 5;
    const int lane = threadIdx.x & 31;
    if (wid >= N_NODES) return;

    const int start = g_rowptr[wid];
    const int end   = g_rowptr[wid + 1];

    const float4* H = (const float4*)g_h;   // 32 float4 per row (256 halfs)
    float a[8];
#pragma unroll
    for (int j = 0; j < 8; ++j) a[j] = 0.0f;

    int i = start;
    for (; i + 3 < end; i += 4) {
        int2 e0 = __ldg(&g_ecv[i]);
        int2 e1 = __ldg(&g_ecv[i + 1]);
        int2 e2 = __ldg(&g_ecv[i + 2]);
        int2 e3 = __ldg(&g_ecv[i + 3]);
        float4 r0 = __ldg(H + (size_t)e0.x * 32 + lane);
        float4 r1 = __ldg(H + (size_t)e1.x * 32 + lane);
        float4 r2 = __ldg(H + (size_t)e2.x * 32 + lane);
        float4 r3 = __ldg(H + (size_t)e3.x * 32 + lane);
        float v0 = __int_as_float(e0.y), v1 = __int_as_float(e1.y);
        float v2 = __int_as_float(e2.y), v3 = __int_as_float(e3.y);

        const __half2* p0 = (const __half2*)&r0;
        const __half2* p1 = (const __half2*)&r1;
        const __half2* p2 = (const __half2*)&r2;
        const __half2* p3 = (const __half2*)&r3;
#pragma unroll
        for (int j = 0; j < 4; ++j) {
            float2 f0 = __half22float2(p0[j]);
            float2 f1 = __half22float2(p1[j]);
            float2 f2 = __half22float2(p2[j]);
            float2 f3 = __half22float2(p3[j]);
            a[2*j]   = fmaf(v0, f0.x, fmaf(v1, f1.x, fmaf(v2, f2.x, fmaf(v3, f3.x, a[2*j]))));
            a[2*j+1] = fmaf(v0, f0.y, fmaf(v1, f1.y, fmaf(v2, f2.y, fmaf(v3, f3.y, a[2*j+1]))));
        }
    }
    for (; i < end; ++i) {
        int2 e0 = __ldg(&g_ecv[i]);
        float4 r0 = __ldg(H + (size_t)e0.x * 32 + lane);
        float v0 = __int_as_float(e0.y);
        const __half2* p0 = (const __half2*)&r0;
#pragma unroll
        for (int j = 0; j < 4; ++j) {
            float2 f0 = __half22float2(p0[j]);
            a[2*j]   = fmaf(v0, f0.x, a[2*j]);
            a[2*j+1] = fmaf(v0, f0.y, a[2*j+1]);
        }
    }

    const float s = g_dinv[wid];
    const float4* bias4 = (const float4*)bias;
    float4 b0 = __ldg(bias4 + lane * 2);
    float4 b1 = __ldg(bias4 + lane * 2 + 1);

    float4 o0, o1;
    o0.x = fmaxf(fmaf(a[0], s, b0.x), 0.0f);
    o0.y = fmaxf(fmaf(a[1], s, b0.y), 0.0f);
    o0.z = fmaxf(fmaf(a[2], s, b0.z), 0.0f);
    o0.w = fmaxf(fmaf(a[3], s, b0.w), 0.0f);
    o1.x = fmaxf(fmaf(a[4], s, b1.x), 0.0f);
    o1.y = fmaxf(fmaf(a[5], s, b1.y), 0.0f);
    o1.z = fmaxf(fmaf(a[6], s, b1.z), 0.0f);
    o1.w = fmaxf(fmaf(a[7], s, b1.w), 0.0f);

    float4* op = (float4*)(out + (size_t)wid * FILTERS) + lane * 2;
    op[0] = o0;
    op[1] = o1;
}

// ---------------------------------------------------------------
extern "C" void kernel_launch(void* const* d_in, const int* in_sizes, int n_in,
                              void* d_out, int out_size) {
    const float* x        = (const float*)d_in[0];
    const int*   edge_row = (const int*)d_in[1];
    const int*   edge_col = (const int*)d_in[2];
    const float* edge_val = (const float*)d_in[3];
    const float* w        = (const float*)d_in[4];
    const float* b        = (const float*)d_in[5];
    float*       out      = (float*)d_out;

    cudaFuncSetAttribute(gemm_wmma_kernel,
                         cudaFuncAttributeMaxDynamicSharedMemorySize, GEMM_SMEM);

    // 1) counts + weighted degree
    zero_kernel<<<NBLK, 256>>>();
    hist_kernel<<<(N_EDGES + 255) / 256, 256>>>(edge_row, edge_val);
    dinv_kernel<<<NBLK, 256>>>();

    // 2) CSR build: scan + fill
    scanA_kernel<<<NBLK, 256>>>();
    scanB_kernel<<<1, 512>>>();
    scanC_kernel<<<NBLK, 256>>>();
    fill_kernel<<<(N_EDGES + 255) / 256, 256>>>(edge_row, edge_col, edge_val);

    // 3) hi/lo fp16 splits of w (transposed) and x
    wsplit_kernel<<<(D_FEAT * FILTERS + 255) / 256, 256>>>(w);
    xsplit_kernel<<<(N_NODES * D_FEAT / 8 + 255) / 256, 256>>>(x);

    // 4) HMMA GEMM: g_h = (half) dinv * (x @ w), 3-term compensated fp16
    gemm_wmma_kernel<<<(N_NODES + BMW - 1) / BMW, 256, GEMM_SMEM>>>();

    // 5) CSR aggregation with fused dinv/bias/relu epilogue
    agg_kernel<<<(N_NODES * 32 + 255) / 256, 256>>>(out, b);
}